// round 16
// baseline (speedup 1.0000x reference)
#include <cuda_runtime.h>
#include <cstdint>

// ============================================================
// BASE MoE layer (sm_103 plain-target: fp16 m16n8k16 mma.sync, fp32 accum)
// out[t] = x[t] + sigmoid(score)*( relu(LN_e(x) W1e^T + b1e) W2e^T + b2e )
// R16: R15 with alignment-legal padding: PADA/PADB = 20 words (80 B,
//      16B-aligned for cp.async; gcd(20,32)=4 -> 2-way max conflicts).
//      B fp16 convert-on-load; one sync/iter; 64x256 CTA tiles.
// ============================================================

#define TOKS 1024
#define DDIM 1024
#define FDIM 4096
#define NEXP 8
#define ROWS_PAD 1152
#define MAX_MT 32
#define KSPLIT 4
#define STAGES 3                          // A cp.async stages
#define PADA 20                           // A: 16 words + 4 pad (16B-aligned stride)
#define PADB 20                           // B: 16 words + 4 pad
#define STAGE_A_WORDS (64 * PADA)         // 1280 words = 5120 B
#define STAGE_B_WORDS (256 * PADB)        // 5120 words = 20480 B
#define SMEM_GEMM ((STAGES * STAGE_A_WORDS + 2 * STAGE_B_WORDS) * 4)  // 56320 B
#define CTA_THREADS 256

// -------------------- device scratch --------------------
// A operands: packed fp16x2 words, permuted [0,4,1,5,2,6,3,7] per 8-word group
__device__ uint32_t g_xn[ROWS_PAD * DDIM / 2];
__device__ uint32_t g_H [ROWS_PAD * FDIM / 2];
__device__ float    g_part[KSPLIT * ROWS_PAD * DDIM];
__device__ float g_mean[TOKS], g_rstd[TOKS], g_alpha[TOKS];
__device__ float g_alpha_s[TOKS];
__device__ int   g_eid[TOKS], g_eid_s[TOKS], g_tok[TOKS];
__device__ int   g_mt_e[MAX_MT], g_mt_r0[MAX_MT], g_mt_r1[MAX_MT];
__device__ int   g_num_mt;

// -------------------- PTX helpers --------------------
__device__ __forceinline__ void cp16(uint32_t dst, const void* src) {
    asm volatile("cp.async.cg.shared.global [%0], [%1], 16;" :: "r"(dst), "l"(src));
}
__device__ __forceinline__ void cp_commit() {
    asm volatile("cp.async.commit_group;" ::: "memory");
}
__device__ __forceinline__ void cp_wait1() {
    asm volatile("cp.async.wait_group 1;" ::: "memory");
}
// pack (lo, hi) floats -> fp16x2 word (lower 16 bits = lo)
__device__ __forceinline__ uint32_t pack_f16(float lo, float hi) {
    uint32_t r;
    asm("cvt.rn.f16x2.f32 %0, %1, %2;" : "=r"(r) : "f"(hi), "f"(lo));
    return r;
}
__device__ __forceinline__ void mma_f16(float* c, const uint32_t* a, const uint32_t* b) {
    asm volatile(
        "mma.sync.aligned.m16n8k16.row.col.f32.f16.f16.f32 "
        "{%0,%1,%2,%3}, {%4,%5,%6,%7}, {%8,%9}, {%0,%1,%2,%3};"
        : "+f"(c[0]), "+f"(c[1]), "+f"(c[2]), "+f"(c[3])
        : "r"(a[0]), "r"(a[1]), "r"(a[2]), "r"(a[3]), "r"(b[0]), "r"(b[1]));
}
// permuted position of logical word j within its 8-word group: [0,4,1,5,2,6,3,7]
__device__ __forceinline__ int pidx(int j) { return ((j & 3) << 1) | ((j & 4) >> 2); }

// -------------------- routing --------------------
__global__ void route_kernel(const float* __restrict__ x, const float* __restrict__ cent) {
    int t = blockIdx.x, tid = threadIdx.x;
    const float4* xr = (const float4*)(x + (size_t)t * DDIM);
    float sum = 0.f, sq = 0.f, acc[NEXP];
#pragma unroll
    for (int e = 0; e < NEXP; e++) acc[e] = 0.f;
    for (int i = tid; i < DDIM / 4; i += 128) {
        float4 xv = xr[i];
#pragma unroll
        for (int e = 0; e < NEXP; e++) {
            float4 cv = ((const float4*)cent)[e * (DDIM / 4) + i];
            acc[e] += xv.x * cv.x + xv.y * cv.y + xv.z * cv.z + xv.w * cv.w;
        }
        sum += xv.x + xv.y + xv.z + xv.w;
        sq  += xv.x * xv.x + xv.y * xv.y + xv.z * xv.z + xv.w * xv.w;
    }
#pragma unroll
    for (int o = 16; o > 0; o >>= 1) {
        sum += __shfl_xor_sync(0xffffffffu, sum, o);
        sq  += __shfl_xor_sync(0xffffffffu, sq,  o);
#pragma unroll
        for (int e = 0; e < NEXP; e++) acc[e] += __shfl_xor_sync(0xffffffffu, acc[e], o);
    }
    __shared__ float sh[4][NEXP + 2];
    int wid = tid >> 5, lid = tid & 31;
    if (lid == 0) {
        sh[wid][0] = sum; sh[wid][1] = sq;
#pragma unroll
        for (int e = 0; e < NEXP; e++) sh[wid][2 + e] = acc[e];
    }
    __syncthreads();
    if (tid == 0) {
        float s = 0.f, q = 0.f, a[NEXP];
#pragma unroll
        for (int e = 0; e < NEXP; e++) a[e] = 0.f;
        for (int w = 0; w < 4; w++) {
            s += sh[w][0]; q += sh[w][1];
#pragma unroll
            for (int e = 0; e < NEXP; e++) a[e] += sh[w][2 + e];
        }
        float mu  = s * (1.f / DDIM);
        float var = q * (1.f / DDIM) - mu * mu;
        g_mean[t] = mu;
        g_rstd[t] = rsqrtf(var + 1e-5f);
        int be = 0; float bs = a[0];
#pragma unroll
        for (int e = 1; e < NEXP; e++) if (a[e] > bs) { bs = a[e]; be = e; }
        g_eid[t]   = be;
        g_alpha[t] = 1.f / (1.f + expf(-bs));
    }
}

// -------------------- counting sort + 64-row m-tile descriptors -------------
__global__ void sort_kernel() {
    __shared__ int cnt[NEXP], ctr[NEXP];
    int t = threadIdx.x;
    if (t < NEXP) cnt[t] = 0;
    __syncthreads();
    int e = g_eid[t];
    atomicAdd(&cnt[e], 1);
    __syncthreads();
    if (t == 0) {
        int o = 0, nm = 0;
        for (int k = 0; k < NEXP; k++) {
            ctr[k] = o;
            int c = cnt[k];
            for (int i = 0; i < c; i += 64) {
                g_mt_e[nm]  = k;
                g_mt_r0[nm] = o + i;
                g_mt_r1[nm] = o + ((i + 64 < c) ? (i + 64) : c);
                nm++;
            }
            o += c;
        }
        g_num_mt = nm;
    }
    __syncthreads();
    int pos = atomicAdd(&ctr[e], 1);
    g_tok[pos] = t;
    g_eid_s[pos] = e;
    g_alpha_s[pos] = g_alpha[t];
}

// -------------------- LN scatter (fp16-packed, word-permuted) ----------------
__global__ void ln_kernel(const float* __restrict__ x, const float* __restrict__ gamma,
                          const float* __restrict__ beta) {
    int p = blockIdx.x, tid = threadIdx.x;
    int t = g_tok[p], e = g_eid_s[p];
    float mu = g_mean[t], rs = g_rstd[t];
    const float4* xr = (const float4*)(x + (size_t)t * DDIM);
    const float4* gr = (const float4*)(gamma + (size_t)e * DDIM);
    const float4* br = (const float4*)(beta + (size_t)e * DDIM);
    uint32_t* o = g_xn + (size_t)p * (DDIM / 2);
    for (int i = tid; i < DDIM / 4; i += 128) {
        float4 xv = xr[i], gv = gr[i], bv = br[i];
        float v0 = (xv.x - mu) * rs * gv.x + bv.x;
        float v1 = (xv.y - mu) * rs * gv.y + bv.y;
        float v2 = (xv.z - mu) * rs * gv.z + bv.z;
        float v3 = (xv.w - mu) * rs * gv.w + bv.w;
        int w0 = 2 * i, w1 = 2 * i + 1;
        int base = w0 & ~7;
        o[base + pidx(w0 & 7)] = pack_f16(v0, v1);
        o[base + pidx(w1 & 7)] = pack_f16(v2, v3);
    }
}

// -------------------- grouped GEMM (fp16 k16, 64x256 CTA, fp16 B slots) ----
// A fp16-packed permuted words (g_xn / g_H); W fp32 [E][N][K] converted
// to fp16 permuted in the load path (LDG prefetch -> cvt -> STS).
// MODE 1: g_H = relu(A W^T + b), fp16-packed permuted store
// MODE 2: g_part[z] = partial(A W^T) over K chunk z (fp32)
template<int KCHUNK, int KFULL, int NDIM, int MODE>
__global__ void __launch_bounds__(CTA_THREADS, 2) gemm_mma(
    const uint32_t* __restrict__ A, const float* __restrict__ W,
    const float* __restrict__ bias, void* __restrict__ outv)
{
    int mt = blockIdx.y;
    if (mt >= g_num_mt) return;
    int e = g_mt_e[mt], row0 = g_mt_r0[mt], row1 = g_mt_r1[mt];
    int n0 = blockIdx.x * 256;
    int bz = blockIdx.z;
    const int KW = KFULL / 2;            // A row stride in words
    int k0w = bz * (KCHUNK / 2);

    extern __shared__ uint32_t shw[];
    uint32_t sA;
    asm("{ .reg .u64 t; cvta.to.shared.u64 t, %1; cvt.u32.u64 %0, t; }"
        : "=r"(sA) : "l"(shw));
    const uint32_t* shA = shw;                         // 3 A stages
    uint32_t* shB = shw + STAGES * STAGE_A_WORDS;      // 2 B slots

    int tid = threadIdx.x;
    int lane = tid & 31, wid = tid >> 5;      // 8 warps, 1 x 8 grid
    int wn = wid;                             // warp tile 64 x 32 at col wn*32
    int lg = lane >> 2, lt = lane & 3;

    const int KT = KCHUNK / 32;

    float acc[4][4][4];                        // 64 registers
#pragma unroll
    for (int a = 0; a < 4; a++)
#pragma unroll
        for (int b = 0; b < 4; b++)
#pragma unroll
            for (int c = 0; c < 4; c++) acc[a][b][c] = 0.f;

    const uint32_t* Abase = A + (size_t)row0 * KW + k0w;
    const float*    Wbase = W + ((size_t)e * NDIM + n0) * KFULL + bz * KCHUNK;

    // ---- A: cp.async stages ----
    auto load_stageA = [&](int it, int s) {
        if (it < KT) {
            int kk0w = it * 16;
            uint32_t dA = sA + s * (STAGE_A_WORDS * 4);
            int r = tid >> 2, c = tid & 3;     // 64 rows x 4 chunks
            cp16(dA + r * (PADA * 4) + c * 16, Abase + (size_t)r * KW + kk0w + c * 4);
        }
        cp_commit();
    };

    // ---- B: register prefetch (converted words) + STS ----
    int brow = tid;                            // 1 row per thread (256 rows)
    const float4* Bg = (const float4*)(Wbase + (size_t)brow * KFULL);
    uint32_t bw[16];                           // converted fp16x2 words, permuted-ready

    auto ldgB = [&](int it) {
        if (it < KT) {
            const float4* p = Bg + it * 8;     // it*32 floats
#pragma unroll
            for (int g = 0; g < 2; g++) {
                float4 q0 = p[4 * g + 0], q1 = p[4 * g + 1];
                float4 q2 = p[4 * g + 2], q3 = p[4 * g + 3];
                // pairs at positions (2m, 2m+1) = logical words (m, m+4)
                bw[8 * g + 0] = pack_f16(q0.x, q0.y);  bw[8 * g + 1] = pack_f16(q2.x, q2.y);
                bw[8 * g + 2] = pack_f16(q0.z, q0.w);  bw[8 * g + 3] = pack_f16(q2.z, q2.w);
                bw[8 * g + 4] = pack_f16(q1.x, q1.y);  bw[8 * g + 5] = pack_f16(q3.x, q3.y);
                bw[8 * g + 6] = pack_f16(q1.z, q1.w);  bw[8 * g + 7] = pack_f16(q3.z, q3.w);
            }
        }
    };
    auto stsB = [&](int it) {
        if (it < KT) {
            uint32_t* d = shB + (it & 1) * STAGE_B_WORDS + brow * PADB;
#pragma unroll
            for (int j = 0; j < 8; j++)
                *(uint2*)(d + 2 * j) = make_uint2(bw[2 * j], bw[2 * j + 1]);
        }
    };

    // prolog
    ldgB(0);
    stsB(0);
    ldgB(1);
    load_stageA(0, 0);
    load_stageA(1, 1);

    for (int it = 0; it < KT; it++) {
        cp_wait1();
        __syncthreads();          // A stage it ready; B slot it&1 visible; slot (it+1)&1 free

        stsB(it + 1);             // bw holds B(it+1)
        ldgB(it + 2);             // prefetch next
        load_stageA(it + 2, (it + 2) % STAGES);

        const uint32_t* As = shA + (it % STAGES) * STAGE_A_WORDS;
        const uint32_t* Bs = shB + (it & 1) * STAGE_B_WORDS;

#pragma unroll
        for (int c16 = 0; c16 < 2; c16++) {
            uint32_t afr[4][4];
#pragma unroll
            for (int m = 0; m < 4; m++) {
                const uint32_t* ap = As + (m * 16 + lg) * PADA + c16 * 8 + 2 * lt;
                uint2 p0 = *(const uint2*)ap;                 // row lg
                uint2 p1 = *(const uint2*)(ap + 8 * PADA);    // row lg+8
                afr[m][0] = p0.x; afr[m][2] = p0.y;
                afr[m][1] = p1.x; afr[m][3] = p1.y;
            }
#pragma unroll
            for (int n = 0; n < 4; n++) {
                const uint32_t* bp = Bs + (wn * 32 + n * 8 + lg) * PADB + c16 * 8 + 2 * lt;
                uint2 bv = *(const uint2*)bp;
                uint32_t bfr[2] = { bv.x, bv.y };
#pragma unroll
                for (int m = 0; m < 4; m++)
                    mma_f16(acc[m][n], afr[m], bfr);
            }
        }
    }

    // -------------------- epilogue --------------------
#pragma unroll
    for (int m = 0; m < 4; m++) {
#pragma unroll
        for (int half = 0; half < 2; half++) {
            int r = m * 16 + half * 8 + lg;
            int p = row0 + r;
            if (p >= row1) continue;
            if (MODE == 1) {
                uint32_t* dst = (uint32_t*)outv + (size_t)p * (NDIM / 2) + n0 / 2;
                const float* bs = bias + (size_t)e * NDIM + n0;
#pragma unroll
                for (int n = 0; n < 4; n++) {
                    int col8 = wn * 32 + n * 8;
                    float v0 = fmaxf(acc[m][n][half * 2 + 0] + bs[col8 + 2 * lt],     0.f);
                    float v1 = fmaxf(acc[m][n][half * 2 + 1] + bs[col8 + 2 * lt + 1], 0.f);
                    int lw = (col8 >> 1) + lt;
                    dst[(lw & ~7) + pidx(lw & 7)] = pack_f16(v0, v1);
                }
            } else {
                float* dst = (float*)outv + ((size_t)bz * ROWS_PAD + p) * NDIM + n0;
#pragma unroll
                for (int n = 0; n < 4; n++) {
                    int col = wn * 32 + n * 8 + 2 * lt;
                    float2 o;
                    o.x = acc[m][n][half * 2 + 0];
                    o.y = acc[m][n][half * 2 + 1];
                    *(float2*)(dst + col) = o;
                }
            }
        }
    }
}

// -------------------- split-K combine + gated residual --------------------
__global__ void combine_kernel(const float* __restrict__ x, const float* __restrict__ b2,
                               float* __restrict__ out) {
    int p = blockIdx.x, tid = threadIdx.x;
    int t = g_tok[p], e = g_eid_s[p];
    float al = g_alpha_s[p];
    const float4* xr = (const float4*)(x + (size_t)t * DDIM);
    const float4* bs = (const float4*)(b2 + (size_t)e * DDIM);
    float4* dst = (float4*)(out + (size_t)t * DDIM);
    for (int i = tid; i < DDIM / 4; i += 128) {
        float4 s = ((const float4*)(g_part + (size_t)p * DDIM))[i];
#pragma unroll
        for (int z = 1; z < KSPLIT; z++) {
            float4 v = ((const float4*)(g_part + ((size_t)z * ROWS_PAD + p) * DDIM))[i];
            s.x += v.x; s.y += v.y; s.z += v.z; s.w += v.w;
        }
        float4 xv = xr[i], bv = bs[i], o;
        o.x = xv.x + al * (s.x + bv.x);
        o.y = xv.y + al * (s.y + bv.y);
        o.z = xv.z + al * (s.z + bv.z);
        o.w = xv.w + al * (s.w + bv.w);
        dst[i] = o;
    }
}

// -------------------- host --------------------
extern "C" void kernel_launch(void* const* d_in, const int* in_sizes, int n_in,
                              void* d_out, int out_size) {
    const float* x     = (const float*)d_in[0];
    const float* cent  = (const float*)d_in[1];
    const float* gamma = (const float*)d_in[2];
    const float* beta  = (const float*)d_in[3];
    const float* W1    = (const float*)d_in[4];
    const float* b1    = (const float*)d_in[5];
    const float* W2    = (const float*)d_in[6];
    const float* b2    = (const float*)d_in[7];
    float* out = (float*)d_out;

    void* pxn = nullptr; void* pH = nullptr; void* ppart = nullptr;
    cudaGetSymbolAddress(&pxn, g_xn);
    cudaGetSymbolAddress(&pH,  g_H);
    cudaGetSymbolAddress(&ppart, g_part);

    cudaFuncSetAttribute((const void*)gemm_mma<DDIM, DDIM, FDIM, 1>,
                         cudaFuncAttributeMaxDynamicSharedMemorySize, SMEM_GEMM);
    cudaFuncSetAttribute((const void*)gemm_mma<FDIM / KSPLIT, FDIM, DDIM, 2>,
                         cudaFuncAttributeMaxDynamicSharedMemorySize, SMEM_GEMM);

    route_kernel<<<TOKS, 128>>>(x, cent);
    sort_kernel<<<1, TOKS>>>();
    ln_kernel<<<TOKS, 128>>>(x, gamma, beta);
    gemm_mma<DDIM, DDIM, FDIM, 1><<<dim3(FDIM / 256, MAX_MT, 1), CTA_THREADS, SMEM_GEMM>>>(
        (const uint32_t*)pxn, W1, b1, pH);
    gemm_mma<FDIM / KSPLIT, FDIM, DDIM, 2><<<dim3(DDIM / 256, MAX_MT, KSPLIT), CTA_THREADS, SMEM_GEMM>>>(
        (const uint32_t*)pH, W2, nullptr, ppart);
    combine_kernel<<<TOKS, 128>>>(x, b2, out);
}

// round 17
// speedup vs baseline: 1.5815x; 1.5815x over previous
#include <cuda_runtime.h>
#include <cstdint>

// ============================================================
// BASE MoE layer (sm_103 plain-target: fp16 m16n8k16 mma.sync, fp32 accum)
// out[t] = x[t] + sigmoid(score)*( relu(LN_e(x) W1e^T + b1e) W2e^T + b2e )
// R17: R16 with the B global load COALESCED (8 lanes/row; was 1 row/
//      thread -> 32 L1tex wavefronts per LDG, the real R14/R16 killer).
//      B fp16 stored unpermuted (consecutive-k pairs), fragments =
//      2x LDS.32, no cvt. One sync/iter. 64x256 CTA tiles.
// ============================================================

#define TOKS 1024
#define DDIM 1024
#define FDIM 4096
#define NEXP 8
#define ROWS_PAD 1152
#define MAX_MT 32
#define KSPLIT 4
#define STAGES 3                          // A cp.async stages
#define PADA 20                           // A: 16 words + 4 pad (80B = 5*16B, cp.async-legal)
#define PADB 18                           // B: 16 words + 2 pad (72B, 8B-aligned, gcd(18,32)=2)
#define STAGE_A_WORDS (64 * PADA)         // 1280 words = 5120 B
#define STAGE_B_WORDS (256 * PADB)        // 4608 words = 18432 B
#define SMEM_GEMM ((STAGES * STAGE_A_WORDS + 2 * STAGE_B_WORDS) * 4)  // 52224 B
#define CTA_THREADS 256

// -------------------- device scratch --------------------
// A operands: packed fp16x2 words, permuted [0,4,1,5,2,6,3,7] per 8-word group
__device__ uint32_t g_xn[ROWS_PAD * DDIM / 2];
__device__ uint32_t g_H [ROWS_PAD * FDIM / 2];
__device__ float    g_part[KSPLIT * ROWS_PAD * DDIM];
__device__ float g_mean[TOKS], g_rstd[TOKS], g_alpha[TOKS];
__device__ float g_alpha_s[TOKS];
__device__ int   g_eid[TOKS], g_eid_s[TOKS], g_tok[TOKS];
__device__ int   g_mt_e[MAX_MT], g_mt_r0[MAX_MT], g_mt_r1[MAX_MT];
__device__ int   g_num_mt;

// -------------------- PTX helpers --------------------
__device__ __forceinline__ void cp16(uint32_t dst, const void* src) {
    asm volatile("cp.async.cg.shared.global [%0], [%1], 16;" :: "r"(dst), "l"(src));
}
__device__ __forceinline__ void cp_commit() {
    asm volatile("cp.async.commit_group;" ::: "memory");
}
__device__ __forceinline__ void cp_wait1() {
    asm volatile("cp.async.wait_group 1;" ::: "memory");
}
// pack (lo, hi) floats -> fp16x2 word (lower 16 bits = lo)
__device__ __forceinline__ uint32_t pack_f16(float lo, float hi) {
    uint32_t r;
    asm("cvt.rn.f16x2.f32 %0, %1, %2;" : "=r"(r) : "f"(hi), "f"(lo));
    return r;
}
__device__ __forceinline__ void mma_f16(float* c, const uint32_t* a, const uint32_t* b) {
    asm volatile(
        "mma.sync.aligned.m16n8k16.row.col.f32.f16.f16.f32 "
        "{%0,%1,%2,%3}, {%4,%5,%6,%7}, {%8,%9}, {%0,%1,%2,%3};"
        : "+f"(c[0]), "+f"(c[1]), "+f"(c[2]), "+f"(c[3])
        : "r"(a[0]), "r"(a[1]), "r"(a[2]), "r"(a[3]), "r"(b[0]), "r"(b[1]));
}
// permuted position of logical word j within its 8-word group: [0,4,1,5,2,6,3,7]
__device__ __forceinline__ int pidx(int j) { return ((j & 3) << 1) | ((j & 4) >> 2); }

// -------------------- routing --------------------
__global__ void route_kernel(const float* __restrict__ x, const float* __restrict__ cent) {
    int t = blockIdx.x, tid = threadIdx.x;
    const float4* xr = (const float4*)(x + (size_t)t * DDIM);
    float sum = 0.f, sq = 0.f, acc[NEXP];
#pragma unroll
    for (int e = 0; e < NEXP; e++) acc[e] = 0.f;
    for (int i = tid; i < DDIM / 4; i += 128) {
        float4 xv = xr[i];
#pragma unroll
        for (int e = 0; e < NEXP; e++) {
            float4 cv = ((const float4*)cent)[e * (DDIM / 4) + i];
            acc[e] += xv.x * cv.x + xv.y * cv.y + xv.z * cv.z + xv.w * cv.w;
        }
        sum += xv.x + xv.y + xv.z + xv.w;
        sq  += xv.x * xv.x + xv.y * xv.y + xv.z * xv.z + xv.w * xv.w;
    }
#pragma unroll
    for (int o = 16; o > 0; o >>= 1) {
        sum += __shfl_xor_sync(0xffffffffu, sum, o);
        sq  += __shfl_xor_sync(0xffffffffu, sq,  o);
#pragma unroll
        for (int e = 0; e < NEXP; e++) acc[e] += __shfl_xor_sync(0xffffffffu, acc[e], o);
    }
    __shared__ float sh[4][NEXP + 2];
    int wid = tid >> 5, lid = tid & 31;
    if (lid == 0) {
        sh[wid][0] = sum; sh[wid][1] = sq;
#pragma unroll
        for (int e = 0; e < NEXP; e++) sh[wid][2 + e] = acc[e];
    }
    __syncthreads();
    if (tid == 0) {
        float s = 0.f, q = 0.f, a[NEXP];
#pragma unroll
        for (int e = 0; e < NEXP; e++) a[e] = 0.f;
        for (int w = 0; w < 4; w++) {
            s += sh[w][0]; q += sh[w][1];
#pragma unroll
            for (int e = 0; e < NEXP; e++) a[e] += sh[w][2 + e];
        }
        float mu  = s * (1.f / DDIM);
        float var = q * (1.f / DDIM) - mu * mu;
        g_mean[t] = mu;
        g_rstd[t] = rsqrtf(var + 1e-5f);
        int be = 0; float bs = a[0];
#pragma unroll
        for (int e = 1; e < NEXP; e++) if (a[e] > bs) { bs = a[e]; be = e; }
        g_eid[t]   = be;
        g_alpha[t] = 1.f / (1.f + expf(-bs));
    }
}

// -------------------- counting sort + 64-row m-tile descriptors -------------
__global__ void sort_kernel() {
    __shared__ int cnt[NEXP], ctr[NEXP];
    int t = threadIdx.x;
    if (t < NEXP) cnt[t] = 0;
    __syncthreads();
    int e = g_eid[t];
    atomicAdd(&cnt[e], 1);
    __syncthreads();
    if (t == 0) {
        int o = 0, nm = 0;
        for (int k = 0; k < NEXP; k++) {
            ctr[k] = o;
            int c = cnt[k];
            for (int i = 0; i < c; i += 64) {
                g_mt_e[nm]  = k;
                g_mt_r0[nm] = o + i;
                g_mt_r1[nm] = o + ((i + 64 < c) ? (i + 64) : c);
                nm++;
            }
            o += c;
        }
        g_num_mt = nm;
    }
    __syncthreads();
    int pos = atomicAdd(&ctr[e], 1);
    g_tok[pos] = t;
    g_eid_s[pos] = e;
    g_alpha_s[pos] = g_alpha[t];
}

// -------------------- LN scatter (fp16-packed, word-permuted) ----------------
__global__ void ln_kernel(const float* __restrict__ x, const float* __restrict__ gamma,
                          const float* __restrict__ beta) {
    int p = blockIdx.x, tid = threadIdx.x;
    int t = g_tok[p], e = g_eid_s[p];
    float mu = g_mean[t], rs = g_rstd[t];
    const float4* xr = (const float4*)(x + (size_t)t * DDIM);
    const float4* gr = (const float4*)(gamma + (size_t)e * DDIM);
    const float4* br = (const float4*)(beta + (size_t)e * DDIM);
    uint32_t* o = g_xn + (size_t)p * (DDIM / 2);
    for (int i = tid; i < DDIM / 4; i += 128) {
        float4 xv = xr[i], gv = gr[i], bv = br[i];
        float v0 = (xv.x - mu) * rs * gv.x + bv.x;
        float v1 = (xv.y - mu) * rs * gv.y + bv.y;
        float v2 = (xv.z - mu) * rs * gv.z + bv.z;
        float v3 = (xv.w - mu) * rs * gv.w + bv.w;
        int w0 = 2 * i, w1 = 2 * i + 1;
        int base = w0 & ~7;
        o[base + pidx(w0 & 7)] = pack_f16(v0, v1);
        o[base + pidx(w1 & 7)] = pack_f16(v2, v3);
    }
}

// -------------------- grouped GEMM (fp16 k16, 64x256 CTA, fp16 B slots) ----
// A fp16-packed permuted words (g_xn / g_H); W fp32 [E][N][K] converted
// to fp16 (unpermuted consecutive-pair words) in the load path with
// COALESCED LDG (8 lanes per row).
// MODE 1: g_H = relu(A W^T + b), fp16-packed permuted store
// MODE 2: g_part[z] = partial(A W^T) over K chunk z (fp32)
template<int KCHUNK, int KFULL, int NDIM, int MODE>
__global__ void __launch_bounds__(CTA_THREADS, 2) gemm_mma(
    const uint32_t* __restrict__ A, const float* __restrict__ W,
    const float* __restrict__ bias, void* __restrict__ outv)
{
    int mt = blockIdx.y;
    if (mt >= g_num_mt) return;
    int e = g_mt_e[mt], row0 = g_mt_r0[mt], row1 = g_mt_r1[mt];
    int n0 = blockIdx.x * 256;
    int bz = blockIdx.z;
    const int KW = KFULL / 2;            // A row stride in words
    int k0w = bz * (KCHUNK / 2);

    extern __shared__ uint32_t shw[];
    uint32_t sA;
    asm("{ .reg .u64 t; cvta.to.shared.u64 t, %1; cvt.u32.u64 %0, t; }"
        : "=r"(sA) : "l"(shw));
    const uint32_t* shA = shw;                         // 3 A stages
    uint32_t* shB = shw + STAGES * STAGE_A_WORDS;      // 2 B slots

    int tid = threadIdx.x;
    int lane = tid & 31, wid = tid >> 5;      // 8 warps, 1 x 8 grid
    int wn = wid;                             // warp tile 64 x 32 at col wn*32
    int lg = lane >> 2, lt = lane & 3;

    const int KT = KCHUNK / 32;

    float acc[4][4][4];                        // 64 registers
#pragma unroll
    for (int a = 0; a < 4; a++)
#pragma unroll
        for (int b = 0; b < 4; b++)
#pragma unroll
            for (int c = 0; c < 4; c++) acc[a][b][c] = 0.f;

    const uint32_t* Abase = A + (size_t)row0 * KW + k0w;
    const float*    Wbase = W + ((size_t)e * NDIM + n0) * KFULL + bz * KCHUNK;

    // ---- A: cp.async stages ----
    auto load_stageA = [&](int it, int s) {
        if (it < KT) {
            int kk0w = it * 16;
            uint32_t dA = sA + s * (STAGE_A_WORDS * 4);
            int r = tid >> 2, c = tid & 3;     // 64 rows x 4 chunks
            cp16(dA + r * (PADA * 4) + c * 16, Abase + (size_t)r * KW + kk0w + c * 4);
        }
        cp_commit();
    };

    // ---- B: coalesced LDG (8 lanes/row) + cvt + STS ----
    int bsub = tid >> 3;                       // row-within-group 0..31
    int bc   = tid & 7;                        // 16B chunk index 0..7
    uint32_t bw[16];                           // 8 groups x 2 words

    auto ldgB = [&](int it) {
        if (it < KT) {
#pragma unroll
            for (int g = 0; g < 8; g++) {
                int row = g * 32 + bsub;
                const float4* p = (const float4*)Wbase + (size_t)row * (KFULL / 4)
                                 + it * 8 + bc;
                float4 q = *p;                 // k = 4bc .. 4bc+3 (within iter)
                bw[2 * g + 0] = pack_f16(q.x, q.y);
                bw[2 * g + 1] = pack_f16(q.z, q.w);
            }
        }
    };
    auto stsB = [&](int it) {
        if (it < KT) {
            uint32_t* d0 = shB + (it & 1) * STAGE_B_WORDS + bsub * PADB + 2 * bc;
#pragma unroll
            for (int g = 0; g < 8; g++)
                *(uint2*)(d0 + g * 32 * PADB) = make_uint2(bw[2 * g], bw[2 * g + 1]);
        }
    };

    // prolog
    ldgB(0);
    stsB(0);
    ldgB(1);
    load_stageA(0, 0);
    load_stageA(1, 1);

    for (int it = 0; it < KT; it++) {
        cp_wait1();
        __syncthreads();          // A stage it ready; B slot it&1 visible; slot (it+1)&1 free

        stsB(it + 1);             // bw holds B(it+1)
        ldgB(it + 2);             // prefetch next
        load_stageA(it + 2, (it + 2) % STAGES);

        const uint32_t* As = shA + (it % STAGES) * STAGE_A_WORDS;
        const uint32_t* Bs = shB + (it & 1) * STAGE_B_WORDS;

#pragma unroll
        for (int c16 = 0; c16 < 2; c16++) {
            uint32_t afr[4][4];
#pragma unroll
            for (int m = 0; m < 4; m++) {
                const uint32_t* ap = As + (m * 16 + lg) * PADA + c16 * 8 + 2 * lt;
                uint2 p0 = *(const uint2*)ap;                 // row lg
                uint2 p1 = *(const uint2*)(ap + 8 * PADA);    // row lg+8
                afr[m][0] = p0.x; afr[m][2] = p0.y;
                afr[m][1] = p1.x; afr[m][3] = p1.y;
            }
#pragma unroll
            for (int n = 0; n < 4; n++) {
                // unpermuted: word lt = k(2lt,2lt+1), word lt+4 = k(2lt+8,2lt+9)
                const uint32_t* bp = Bs + (wn * 32 + n * 8 + lg) * PADB + c16 * 8 + lt;
                uint32_t bfr[2];
                bfr[0] = bp[0];
                bfr[1] = bp[4];
#pragma unroll
                for (int m = 0; m < 4; m++)
                    mma_f16(acc[m][n], afr[m], bfr);
            }
        }
    }

    // -------------------- epilogue --------------------
#pragma unroll
    for (int m = 0; m < 4; m++) {
#pragma unroll
        for (int half = 0; half < 2; half++) {
            int r = m * 16 + half * 8 + lg;
            int p = row0 + r;
            if (p >= row1) continue;
            if (MODE == 1) {
                uint32_t* dst = (uint32_t*)outv + (size_t)p * (NDIM / 2) + n0 / 2;
                const float* bs = bias + (size_t)e * NDIM + n0;
#pragma unroll
                for (int n = 0; n < 4; n++) {
                    int col8 = wn * 32 + n * 8;
                    float v0 = fmaxf(acc[m][n][half * 2 + 0] + bs[col8 + 2 * lt],     0.f);
                    float v1 = fmaxf(acc[m][n][half * 2 + 1] + bs[col8 + 2 * lt + 1], 0.f);
                    int lw = (col8 >> 1) + lt;
                    dst[(lw & ~7) + pidx(lw & 7)] = pack_f16(v0, v1);
                }
            } else {
                float* dst = (float*)outv + ((size_t)bz * ROWS_PAD + p) * NDIM + n0;
#pragma unroll
                for (int n = 0; n < 4; n++) {
                    int col = wn * 32 + n * 8 + 2 * lt;
                    float2 o;
                    o.x = acc[m][n][half * 2 + 0];
                    o.y = acc[m][n][half * 2 + 1];
                    *(float2*)(dst + col) = o;
                }
            }
        }
    }
}

// -------------------- split-K combine + gated residual --------------------
__global__ void combine_kernel(const float* __restrict__ x, const float* __restrict__ b2,
                               float* __restrict__ out) {
    int p = blockIdx.x, tid = threadIdx.x;
    int t = g_tok[p], e = g_eid_s[p];
    float al = g_alpha_s[p];
    const float4* xr = (const float4*)(x + (size_t)t * DDIM);
    const float4* bs = (const float4*)(b2 + (size_t)e * DDIM);
    float4* dst = (float4*)(out + (size_t)t * DDIM);
    for (int i = tid; i < DDIM / 4; i += 128) {
        float4 s = ((const float4*)(g_part + (size_t)p * DDIM))[i];
#pragma unroll
        for (int z = 1; z < KSPLIT; z++) {
            float4 v = ((const float4*)(g_part + ((size_t)z * ROWS_PAD + p) * DDIM))[i];
            s.x += v.x; s.y += v.y; s.z += v.z; s.w += v.w;
        }
        float4 xv = xr[i], bv = bs[i], o;
        o.x = xv.x + al * (s.x + bv.x);
        o.y = xv.y + al * (s.y + bv.y);
        o.z = xv.z + al * (s.z + bv.z);
        o.w = xv.w + al * (s.w + bv.w);
        dst[i] = o;
    }
}

// -------------------- host --------------------
extern "C" void kernel_launch(void* const* d_in, const int* in_sizes, int n_in,
                              void* d_out, int out_size) {
    const float* x     = (const float*)d_in[0];
    const float* cent  = (const float*)d_in[1];
    const float* gamma = (const float*)d_in[2];
    const float* beta  = (const float*)d_in[3];
    const float* W1    = (const float*)d_in[4];
    const float* b1    = (const float*)d_in[5];
    const float* W2    = (const float*)d_in[6];
    const float* b2    = (const float*)d_in[7];
    float* out = (float*)d_out;

    void* pxn = nullptr; void* pH = nullptr; void* ppart = nullptr;
    cudaGetSymbolAddress(&pxn, g_xn);
    cudaGetSymbolAddress(&pH,  g_H);
    cudaGetSymbolAddress(&ppart, g_part);

    cudaFuncSetAttribute((const void*)gemm_mma<DDIM, DDIM, FDIM, 1>,
                         cudaFuncAttributeMaxDynamicSharedMemorySize, SMEM_GEMM);
    cudaFuncSetAttribute((const void*)gemm_mma<FDIM / KSPLIT, FDIM, DDIM, 2>,
                         cudaFuncAttributeMaxDynamicSharedMemorySize, SMEM_GEMM);

    route_kernel<<<TOKS, 128>>>(x, cent);
    sort_kernel<<<1, TOKS>>>();
    ln_kernel<<<TOKS, 128>>>(x, gamma, beta);
    gemm_mma<DDIM, DDIM, FDIM, 1><<<dim3(FDIM / 256, MAX_MT, 1), CTA_THREADS, SMEM_GEMM>>>(
        (const uint32_t*)pxn, W1, b1, pH);
    gemm_mma<FDIM / KSPLIT, FDIM, DDIM, 2><<<dim3(DDIM / 256, MAX_MT, KSPLIT), CTA_THREADS, SMEM_GEMM>>>(
        (const uint32_t*)pH, W2, nullptr, ppart);
    combine_kernel<<<TOKS, 128>>>(x, b2, out);
}